// round 1
// baseline (speedup 1.0000x reference)
#include <cuda_runtime.h>
#include <cstdint>
#include <math.h>

// ---------------------------------------------------------------------------
// CARAFE: conv1x1+BN+SiLU -> conv3x3+BN -> pixelshuffle(2) -> softmax(25)
//         -> content-aware 5x5 (dilation 2) reassembly of nearest-up x.
// Shapes: x[8,128,64,64] -> out[8,128,128,128], all fp32.
// ---------------------------------------------------------------------------

#define B 8
#define CIN 128
#define MID 64
#define OC2 100
#define H 64
#define W 64
#define HW 4096
#define EPS 1e-5f

// scratch (device globals: no allocation allowed)
__device__ float g_t1[B * MID * HW];    // conv1 raw output
__device__ float g_t2[B * OC2 * HW];    // conv3 raw output
__device__ float g_sc1[MID], g_sh1[MID];
__device__ float g_sc2[OC2], g_sh2[OC2];

// ---------------------------------------------------------------------------
// Kernel 1: 1x1 conv  t1[b,oc,p] = sum_c x[b,c,p] * w[oc,c]
// grid (16 pixel-tiles, 8 batch), 256 threads.
// thread: 4 pixels (float4) x 16 oc.
// ---------------------------------------------------------------------------
__global__ void k_conv1(const float* __restrict__ x, const float* __restrict__ cw) {
    __shared__ float xs[32][256];
    __shared__ float ws[64][32];
    const int b = blockIdx.y;
    const int p0 = blockIdx.x * 256;
    const int tid = threadIdx.x;
    const int pixg = tid & 63;   // pixel group: pixels pixg*4 .. +3
    const int ocg = tid >> 6;    // oc group: oc = ocg*16 + k

    float acc[16][4];
#pragma unroll
    for (int k = 0; k < 16; k++) {
        acc[k][0] = 0.f; acc[k][1] = 0.f; acc[k][2] = 0.f; acc[k][3] = 0.f;
    }

    for (int c0 = 0; c0 < CIN; c0 += 32) {
        __syncthreads();
#pragma unroll 4
        for (int j = 0; j < 32; j++)
            xs[j][tid] = x[((size_t)(b * CIN + c0 + j) << 12) + p0 + tid];
#pragma unroll
        for (int j = 0; j < 8; j++) {
            int idx = j * 256 + tid;
            int oc = idx >> 5, cc = idx & 31;
            ws[oc][cc] = cw[oc * CIN + c0 + cc];
        }
        __syncthreads();
#pragma unroll 8
        for (int cc = 0; cc < 32; cc++) {
            float4 xv = *(const float4*)&xs[cc][pixg * 4];
#pragma unroll
            for (int k = 0; k < 16; k++) {
                float wv = ws[ocg * 16 + k][cc];
                acc[k][0] = fmaf(wv, xv.x, acc[k][0]);
                acc[k][1] = fmaf(wv, xv.y, acc[k][1]);
                acc[k][2] = fmaf(wv, xv.z, acc[k][2]);
                acc[k][3] = fmaf(wv, xv.w, acc[k][3]);
            }
        }
    }
#pragma unroll
    for (int k = 0; k < 16; k++) {
        int oc = ocg * 16 + k;
        *(float4*)&g_t1[((size_t)(b * MID + oc) << 12) + p0 + pixg * 4] =
            make_float4(acc[k][0], acc[k][1], acc[k][2], acc[k][3]);
    }
}

// ---------------------------------------------------------------------------
// Stats: per-channel mean/var over (N,H,W) -> fused scale/shift.
// One block per channel, 256 threads. Templated on which tensor.
// ---------------------------------------------------------------------------
template <int C>
__global__ void k_stats(const float* __restrict__ gam, const float* __restrict__ bet) {
    const float* t = (C == MID) ? g_t1 : g_t2;
    float* sc = (C == MID) ? g_sc1 : g_sc2;
    float* sh = (C == MID) ? g_sh1 : g_sh2;
    const int oc = blockIdx.x;
    const int tid = threadIdx.x;
    float s = 0.f, s2 = 0.f;
    for (int b = 0; b < B; b++) {
        const float* p = t + ((size_t)(b * C + oc) << 12);
        for (int i = tid; i < HW; i += 256) {
            float v = p[i];
            s += v;
            s2 = fmaf(v, v, s2);
        }
    }
#pragma unroll
    for (int o = 16; o; o >>= 1) {
        s  += __shfl_down_sync(0xFFFFFFFFu, s, o);
        s2 += __shfl_down_sync(0xFFFFFFFFu, s2, o);
    }
    __shared__ float rs[8], rs2[8];
    if ((tid & 31) == 0) { rs[tid >> 5] = s; rs2[tid >> 5] = s2; }
    __syncthreads();
    if (tid == 0) {
        s = 0.f; s2 = 0.f;
#pragma unroll
        for (int i = 0; i < 8; i++) { s += rs[i]; s2 += rs2[i]; }
        const float inv = 1.f / (float)(B * HW);
        float m = s * inv;
        float var = fmaf(-m, m, s2 * inv);
        float k = gam[oc] * rsqrtf(var + EPS);
        sc[oc] = k;
        sh[oc] = bet[oc] - m * k;
    }
}

// ---------------------------------------------------------------------------
// Kernel 3: 3x3 conv (pad 1) on silu(bn(t1)) -> t2 raw.
// grid (32 tiles of 16x8, 8 batch), 256 threads.
// thread: 4 pixels (one row) x up-to-13 strided oc.
// smem (dynamic): inb[16][10][18] + wsm[16*9][100] (+pad)
// ---------------------------------------------------------------------------
#define CONV3_SMEM ((2880 + 14400 + 16) * 4)

__global__ void k_conv3(const float* __restrict__ ew) {
    extern __shared__ float sm[];
    float* inb = sm;            // [cc][10][18]
    float* wsm = sm + 2880;     // [(cc*9+t)][100]

    const int b = blockIdx.y;
    const int ox0 = (blockIdx.x & 3) * 16;
    const int oy0 = (blockIdx.x >> 2) * 8;
    const int tid = threadIdx.x;
    const int pixg = tid & 31;       // pixel p = pixg*4+j
    const int ocg = tid >> 5;        // oc = ocg + 8k
    const int py = pixg >> 2;
    const int pxb = (pixg & 3) * 4;

    float acc[13][4];
#pragma unroll
    for (int k = 0; k < 13; k++) {
        acc[k][0] = 0.f; acc[k][1] = 0.f; acc[k][2] = 0.f; acc[k][3] = 0.f;
    }

    for (int c0 = 0; c0 < MID; c0 += 16) {
        __syncthreads();
        // stage input tile with BN+SiLU applied (zero padding stays zero)
        for (int idx = tid; idx < 2880; idx += 256) {
            int cc = idx / 180;
            int r = idx - cc * 180;
            int y = r / 18;
            int xx = r - y * 18;
            int gy = oy0 - 1 + y, gx = ox0 - 1 + xx;
            float v = 0.f;
            if ((unsigned)gy < 64u && (unsigned)gx < 64u) {
                int c = c0 + cc;
                float raw = g_t1[((size_t)(b * MID + c) << 12) + (gy << 6) + gx];
                float z = fmaf(raw, g_sc1[c], g_sh1[c]);
                v = z / (1.f + expf(-z));
            }
            inb[idx] = v;
        }
        // stage weights: layout [(cc*9 + t)][100]
        for (int idx = tid; idx < 14400; idx += 256) {
            int oc = idx % 100;
            int ct = idx / 100;
            int cc = ct / 9, t = ct - cc * 9;
            wsm[idx] = ew[(oc * MID + c0 + cc) * 9 + t];
        }
        __syncthreads();

#pragma unroll 1
        for (int cc = 0; cc < 16; cc++) {
#pragma unroll
            for (int ky = 0; ky < 3; ky++) {
#pragma unroll
                for (int kx = 0; kx < 3; kx++) {
                    const float* ip = &inb[cc * 180 + (py + ky) * 18 + pxb + kx];
                    float x0 = ip[0], x1 = ip[1], x2 = ip[2], x3 = ip[3];
                    const float* wp = &wsm[(cc * 9 + ky * 3 + kx) * 100 + ocg];
#pragma unroll
                    for (int k = 0; k < 13; k++) {
                        float wv = wp[k << 3];   // warp-uniform broadcast
                        acc[k][0] = fmaf(wv, x0, acc[k][0]);
                        acc[k][1] = fmaf(wv, x1, acc[k][1]);
                        acc[k][2] = fmaf(wv, x2, acc[k][2]);
                        acc[k][3] = fmaf(wv, x3, acc[k][3]);
                    }
                }
            }
        }
    }
#pragma unroll
    for (int k = 0; k < 13; k++) {
        int oc = ocg + (k << 3);
        if (oc < OC2) {
            size_t o = ((size_t)(b * OC2 + oc) << 12) + ((oy0 + py) << 6) + ox0 + pxb;
            *(float4*)&g_t2[o] = make_float4(acc[k][0], acc[k][1], acc[k][2], acc[k][3]);
        }
    }
}

// ---------------------------------------------------------------------------
// Kernel 5: BN + pixelshuffle + softmax + reassembly.
// grid (64 tiles of 16x16 output, 8 batch), 256 threads.
// Identity: tap (dy,dx) at out (i,j) reads x[i/2 + dy - 2, j/2 + dx - 2].
// Phase A: each thread computes softmax weights for one out pixel -> smem.
// Phase B: thread owns column-pair (i, 2qx/2qx+1) sharing one 5x5 window;
//          channels split by parity (stride 2) -> conflict-free LDS.
// smem: srcs[128][144] + wgt[256][25] = 99328 B (dynamic)
// ---------------------------------------------------------------------------
#define REASM_SMEM ((128 * 144 + 256 * 25) * 4)

__global__ void k_reasm(const float* __restrict__ x, float* __restrict__ out) {
    extern __shared__ float sm[];
    float* srcs = sm;               // [c][12][12]
    float* wgt = sm + 128 * 144;    // [pixel][25]

    const int b = blockIdx.y;
    const int ti0 = (blockIdx.x >> 3) << 4;
    const int tj0 = (blockIdx.x & 7) << 4;
    const int tid = threadIdx.x;
    const int sy0 = (ti0 >> 1) - 2;
    const int sx0 = (tj0 >> 1) - 2;

    // stage x window (zero padding)
    for (int idx = tid; idx < 128 * 144; idx += 256) {
        int c = idx / 144;
        int r = idx - c * 144;
        int yy = r / 12;
        int xx = r - yy * 12;
        int gy = sy0 + yy, gx = sx0 + xx;
        float v = 0.f;
        if ((unsigned)gy < 64u && (unsigned)gx < 64u)
            v = x[((size_t)(b * CIN + c) << 12) + (gy << 6) + gx];
        srcs[idx] = v;
    }

    // softmax weights for this thread's pixel
    {
        int py = tid >> 4, px = tid & 15;
        int gi = ti0 + py, gj = tj0 + px;
        int y0 = gi >> 1, x0 = gj >> 1;
        int sub = ((gi & 1) << 1) | (gj & 1);
        float l[25];
        float mx = -1e30f;
#pragma unroll
        for (int k = 0; k < 25; k++) {
            int ch = (k << 2) + sub;
            float v = fmaf(g_t2[((size_t)(b * OC2 + ch) << 12) + (y0 << 6) + x0],
                           g_sc2[ch], g_sh2[ch]);
            l[k] = v;
            mx = fmaxf(mx, v);
        }
        float s = 0.f;
#pragma unroll
        for (int k = 0; k < 25; k++) { l[k] = expf(l[k] - mx); s += l[k]; }
        float inv = 1.f / s;
#pragma unroll
        for (int k = 0; k < 25; k++) wgt[tid * 25 + k] = l[k] * inv;
    }
    __syncthreads();

    const int cg = tid & 1;
    const int qx = (tid >> 1) & 7;
    const int i = tid >> 4;

    float w0[25], w1[25];
    {
        const float* wp = &wgt[(i * 16 + 2 * qx) * 25];
#pragma unroll
        for (int k = 0; k < 25; k++) { w0[k] = wp[k]; w1[k] = wp[25 + k]; }
    }

    const float* Sbase = srcs + (i >> 1) * 12 + qx;
    const int gi = ti0 + i;
    const int gj = tj0 + 2 * qx;

#pragma unroll 2
    for (int c = cg; c < CIN; c += 2) {
        const float* S = Sbase + c * 144;
        float a0 = 0.f, a1 = 0.f;
#pragma unroll
        for (int dy = 0; dy < 5; dy++) {
#pragma unroll
            for (int dx = 0; dx < 5; dx++) {
                float sv = S[dy * 12 + dx];
                int k = dy * 5 + dx;
                a0 = fmaf(w0[k], sv, a0);
                a1 = fmaf(w1[k], sv, a1);
            }
        }
        size_t o = (((size_t)(b * CIN + c) * 128 + gi) << 7) + gj;
        *(float2*)&out[o] = make_float2(a0, a1);
    }
}

// ---------------------------------------------------------------------------
extern "C" void kernel_launch(void* const* d_in, const int* in_sizes, int n_in,
                              void* d_out, int out_size) {
    const float* x      = (const float*)d_in[0];
    const float* comp_w = (const float*)d_in[1];
    const float* comp_g = (const float*)d_in[2];
    const float* comp_b = (const float*)d_in[3];
    const float* enc_w  = (const float*)d_in[4];
    const float* enc_g  = (const float*)d_in[5];
    const float* enc_b  = (const float*)d_in[6];
    float* out = (float*)d_out;

    cudaFuncSetAttribute(k_conv3, cudaFuncAttributeMaxDynamicSharedMemorySize, CONV3_SMEM);
    cudaFuncSetAttribute(k_reasm, cudaFuncAttributeMaxDynamicSharedMemorySize, REASM_SMEM);

    k_conv1<<<dim3(16, B), 256>>>(x, comp_w);
    k_stats<MID><<<MID, 256>>>(comp_g, comp_b);
    k_conv3<<<dim3(32, B), 256, CONV3_SMEM>>>(enc_w);
    k_stats<OC2><<<OC2, 256>>>(enc_g, enc_b);
    k_reasm<<<dim3(64, B), 256, REASM_SMEM>>>(x, out);
}

// round 3
// speedup vs baseline: 1.0502x; 1.0502x over previous
#include <cuda_runtime.h>
#include <cstdint>
#include <math.h>

// ---------------------------------------------------------------------------
// CARAFE fp32: conv1x1+BN+SiLU -> conv3x3+BN -> pxshuffle(2) -> softmax(25)
//              -> 5x5 dil-2 content-aware reassembly.  x[8,128,64,64]
// Round 2: f32x2 packed FMA, fused BN stats, packed reassembly.
// ---------------------------------------------------------------------------

#define B 8
#define CIN 128
#define MID 64
#define OC2 100
#define HW 4096
#define EPS 1e-5f

typedef unsigned long long u64;

__device__ __forceinline__ u64 pk(float lo, float hi) {
    u64 r; asm("mov.b64 %0,{%1,%2};" : "=l"(r) : "f"(lo), "f"(hi)); return r;
}
__device__ __forceinline__ void fma2(u64& d, u64 a, u64 b) {
    asm("fma.rn.f32x2 %0,%1,%2,%0;" : "+l"(d) : "l"(a), "l"(b));
}
__device__ __forceinline__ u64 add2(u64 a, u64 b) {
    u64 r; asm("add.rn.f32x2 %0,%1,%2;" : "=l"(r) : "l"(a), "l"(b)); return r;
}
__device__ __forceinline__ void unpk(u64 a, float& lo, float& hi) {
    asm("mov.b64 {%0,%1},%2;" : "=f"(lo), "=f"(hi) : "l"(a));
}

// scratch
__device__ float g_t1[B * MID * HW];
__device__ float g_t2[B * OC2 * HW];
__device__ float g_sc1[MID], g_sh1[MID];
__device__ float g_sc2[OC2], g_sh2[OC2];
__device__ float g_p1s[128 * 64], g_p1q[128 * 64];     // conv1 partials (128 blocks)
__device__ float g_p2s[256 * 100], g_p2q[256 * 100];   // conv3 partials (256 blocks)

__device__ __forceinline__ void wred2(u64& s, u64& q) {
#pragma unroll
    for (int o = 16; o; o >>= 1) {
        s = add2(s, __shfl_down_sync(0xFFFFFFFFu, s, o));
        q = add2(q, __shfl_down_sync(0xFFFFFFFFu, q, o));
    }
}

// ---------------------------------------------------------------------------
// conv1x1: t1[b,oc,p] = sum_c x[b,c,p]*w[oc,c].  grid(16,8) x 256.
// thread: 4 pixels x 8 oc-pairs (packed over oc).  + fused BN partial stats.
// ---------------------------------------------------------------------------
__global__ void k_conv1(const float* __restrict__ x, const float* __restrict__ cw) {
    __shared__ float xs[32][256];
    __shared__ float ws1[32][64];
    __shared__ u64 r_s[8][8], r_q[8][8];
    const int b = blockIdx.y;
    const int p0 = blockIdx.x * 256;
    const int tid = threadIdx.x;
    const int pixg = tid & 63;
    const int ocg = tid >> 6;       // 0..3; uniform per warp-pair

    u64 acc[8][4];
#pragma unroll
    for (int p = 0; p < 8; p++)
#pragma unroll
        for (int j = 0; j < 4; j++) acc[p][j] = 0ull;

    for (int c0 = 0; c0 < CIN; c0 += 32) {
        __syncthreads();
#pragma unroll 4
        for (int j = 0; j < 32; j++)
            xs[j][tid] = x[((size_t)(b * CIN + c0 + j) << 12) + p0 + tid];
#pragma unroll
        for (int j = 0; j < 8; j++) {
            int idx = j * 256 + tid;
            int oc = idx & 63, cc = idx >> 6;
            ws1[cc][oc] = cw[oc * CIN + c0 + cc];
        }
        __syncthreads();
#pragma unroll 4
        for (int cc = 0; cc < 32; cc++) {
            float4 xv = *(const float4*)&xs[cc][pixg * 4];
            u64 P0 = pk(xv.x, xv.x), P1 = pk(xv.y, xv.y);
            u64 P2 = pk(xv.z, xv.z), P3 = pk(xv.w, xv.w);
            const u64* wp = (const u64*)&ws1[cc][ocg * 16];
#pragma unroll
            for (int p = 0; p < 8; p++) {
                u64 w = wp[p];
                fma2(acc[p][0], w, P0);
                fma2(acc[p][1], w, P1);
                fma2(acc[p][2], w, P2);
                fma2(acc[p][3], w, P3);
            }
        }
    }
    // store + packed partial stats
    const int lane = tid & 31, wid = tid >> 5;
#pragma unroll
    for (int p = 0; p < 8; p++) {
        int oce = ocg * 16 + 2 * p;
        float e0, o0, e1, o1, e2, o2, e3, o3;
        unpk(acc[p][0], e0, o0); unpk(acc[p][1], e1, o1);
        unpk(acc[p][2], e2, o2); unpk(acc[p][3], e3, o3);
        *(float4*)&g_t1[((size_t)(b * MID + oce) << 12) + p0 + pixg * 4] =
            make_float4(e0, e1, e2, e3);
        *(float4*)&g_t1[((size_t)(b * MID + oce + 1) << 12) + p0 + pixg * 4] =
            make_float4(o0, o1, o2, o3);
        u64 s = add2(add2(acc[p][0], acc[p][1]), add2(acc[p][2], acc[p][3]));
        u64 q = 0ull;
        fma2(q, acc[p][0], acc[p][0]); fma2(q, acc[p][1], acc[p][1]);
        fma2(q, acc[p][2], acc[p][2]); fma2(q, acc[p][3], acc[p][3]);
        wred2(s, q);
        if (lane == 0) { r_s[wid][p] = s; r_q[wid][p] = q; }
    }
    __syncthreads();
    if (tid < 32) {
        int g = tid >> 3, p = tid & 7;
        u64 s = add2(r_s[2 * g][p], r_s[2 * g + 1][p]);
        u64 q = add2(r_q[2 * g][p], r_q[2 * g + 1][p]);
        int blk = b * 16 + blockIdx.x;
        *(u64*)&g_p1s[blk * 64 + 2 * (g * 8 + p)] = s;
        *(u64*)&g_p1q[blk * 64 + 2 * (g * 8 + p)] = q;
    }
}

// ---------------------------------------------------------------------------
// finalize BN1 / BN2
// ---------------------------------------------------------------------------
__global__ void k_fin1(const float* __restrict__ gam, const float* __restrict__ bet) {
    const int oc = blockIdx.x, t = threadIdx.x;      // 128 threads
    float s = g_p1s[t * 64 + oc], q = g_p1q[t * 64 + oc];
#pragma unroll
    for (int o = 16; o; o >>= 1) {
        s += __shfl_down_sync(0xFFFFFFFFu, s, o);
        q += __shfl_down_sync(0xFFFFFFFFu, q, o);
    }
    __shared__ float ss[4], qq[4];
    if ((t & 31) == 0) { ss[t >> 5] = s; qq[t >> 5] = q; }
    __syncthreads();
    if (t == 0) {
        s = ss[0] + ss[1] + ss[2] + ss[3];
        q = qq[0] + qq[1] + qq[2] + qq[3];
        const float inv = 1.f / 32768.f;
        float m = s * inv, var = fmaf(-m, m, q * inv);
        float k = gam[oc] * rsqrtf(var + EPS);
        g_sc1[oc] = k; g_sh1[oc] = bet[oc] - m * k;
    }
}
__global__ void k_fin2(const float* __restrict__ gam, const float* __restrict__ bet) {
    const int oc = blockIdx.x, t = threadIdx.x;      // 256 threads
    float s = g_p2s[t * 100 + oc], q = g_p2q[t * 100 + oc];
#pragma unroll
    for (int o = 16; o; o >>= 1) {
        s += __shfl_down_sync(0xFFFFFFFFu, s, o);
        q += __shfl_down_sync(0xFFFFFFFFu, q, o);
    }
    __shared__ float ss[8], qq[8];
    if ((t & 31) == 0) { ss[t >> 5] = s; qq[t >> 5] = q; }
    __syncthreads();
    if (t == 0) {
        s = 0.f; q = 0.f;
#pragma unroll
        for (int i = 0; i < 8; i++) { s += ss[i]; q += qq[i]; }
        const float inv = 1.f / 32768.f;
        float m = s * inv, var = fmaf(-m, m, q * inv);
        float k = gam[oc] * rsqrtf(var + EPS);
        g_sc2[oc] = k; g_sh2[oc] = bet[oc] - m * k;
    }
}

// ---------------------------------------------------------------------------
// conv3x3 (pad 1) on silu(bn(t1)) -> t2.  grid(32,8) x 256.
// thread: 4 pixels (one row) x 7 oc-pairs (packed over oc). + fused stats.
// smem: inb[16][10][18] + wsm[144][100] (+pad)
// ---------------------------------------------------------------------------
#define CONV3_SMEM ((2880 + 14400 + 16) * 4)

__global__ __launch_bounds__(256) void k_conv3(const float* __restrict__ ew) {
    extern __shared__ float sm[];
    float* inb = sm;            // [cc][10][18]
    float* wsm = sm + 2880;     // [(cc*9+t)][100] oc-fast

    const int b = blockIdx.y;
    const int ox0 = (blockIdx.x & 3) * 16;
    const int oy0 = (blockIdx.x >> 2) * 8;
    const int tid = threadIdx.x;
    const int pixg = tid & 31;
    const int ocg = tid >> 5;        // warp id 0..7
    const int py = pixg >> 2;
    const int pxb = (pixg & 3) * 4;

    u64 acc[7][4];
#pragma unroll
    for (int k = 0; k < 7; k++)
#pragma unroll
        for (int j = 0; j < 4; j++) acc[k][j] = 0ull;

    for (int c0 = 0; c0 < MID; c0 += 16) {
        __syncthreads();
        for (int idx = tid; idx < 2880; idx += 256) {
            int cc = idx / 180;
            int r = idx - cc * 180;
            int y = r / 18;
            int xx = r - y * 18;
            int gy = oy0 - 1 + y, gx = ox0 - 1 + xx;
            float v = 0.f;
            if ((unsigned)gy < 64u && (unsigned)gx < 64u) {
                int c = c0 + cc;
                float raw = g_t1[((size_t)(b * MID + c) << 12) + (gy << 6) + gx];
                float z = fmaf(raw, g_sc1[c], g_sh1[c]);
                v = z / (1.f + expf(-z));
            }
            inb[idx] = v;
        }
        for (int idx = tid; idx < 14400; idx += 256) {
            int oc = idx % 100;
            int ct = idx / 100;
            int cc = ct / 9, t = ct - cc * 9;
            wsm[idx] = ew[(oc * MID + c0 + cc) * 9 + t];
        }
        __syncthreads();

#pragma unroll 1
        for (int cc = 0; cc < 16; cc++) {
            const float* rb = inb + cc * 180 + pxb;
#pragma unroll
            for (int ky = 0; ky < 3; ky++) {
                const float* rp = rb + (py + ky) * 18;
                float v0 = rp[0], v1 = rp[1], v2 = rp[2],
                      v3 = rp[3], v4 = rp[4], v5 = rp[5];
                u64 P[6];
                P[0] = pk(v0, v0); P[1] = pk(v1, v1); P[2] = pk(v2, v2);
                P[3] = pk(v3, v3); P[4] = pk(v4, v4); P[5] = pk(v5, v5);
#pragma unroll
                for (int kx = 0; kx < 3; kx++) {
                    const u64* wrow =
                        (const u64*)(wsm + (cc * 9 + ky * 3 + kx) * 100) + ocg;
#pragma unroll
                    for (int k = 0; k < 7; k++) {
                        u64 w = wrow[k * 8];        // warp-uniform LDS.64
                        fma2(acc[k][0], w, P[kx]);
                        fma2(acc[k][1], w, P[kx + 1]);
                        fma2(acc[k][2], w, P[kx + 2]);
                        fma2(acc[k][3], w, P[kx + 3]);
                    }
                }
            }
        }
    }

    const int lane = tid & 31;
    const int blk = b * 32 + blockIdx.x;
#pragma unroll
    for (int k = 0; k < 7; k++) {
        bool valid = (k < 6) || (ocg < 2);
        if (!valid) continue;
        int pr = ocg + 8 * k;
        int oce = 2 * pr;
        float e0, o0, e1, o1, e2, o2, e3, o3;
        unpk(acc[k][0], e0, o0); unpk(acc[k][1], e1, o1);
        unpk(acc[k][2], e2, o2); unpk(acc[k][3], e3, o3);
        size_t ob = ((size_t)(b * OC2 + oce) << 12) + ((oy0 + py) << 6) + ox0 + pxb;
        *(float4*)&g_t2[ob] = make_float4(e0, e1, e2, e3);
        *(float4*)&g_t2[ob + HW] = make_float4(o0, o1, o2, o3);
        u64 s = add2(add2(acc[k][0], acc[k][1]), add2(acc[k][2], acc[k][3]));
        u64 q = 0ull;
        fma2(q, acc[k][0], acc[k][0]); fma2(q, acc[k][1], acc[k][1]);
        fma2(q, acc[k][2], acc[k][2]); fma2(q, acc[k][3], acc[k][3]);
        wred2(s, q);                     // warp-uniform participation
        if (lane == 0) {
            *(u64*)&g_p2s[blk * 100 + oce] = s;
            *(u64*)&g_p2q[blk * 100 + oce] = q;
        }
    }
}

// ---------------------------------------------------------------------------
// reassembly: BN2 + pxshuffle + softmax + weighted 5x5 (dil 2) gather.
// grid(64,8) x 256.  smem: srcs2[144 pos][132 ch-padded] + wgt[256][25].
// thread: pixel-pair (i, 2qx / 2qx+1), channel-pairs packed via f32x2.
// ---------------------------------------------------------------------------
#define CS 132
#define REASM_SMEM ((144 * CS + 256 * 25) * 4)

__global__ __launch_bounds__(256, 1) void k_reasm(const float* __restrict__ x,
                                                  float* __restrict__ out) {
    extern __shared__ float sm[];
    float* srcs = sm;                 // [pos][CS]
    float* wgt = sm + 144 * CS;       // [pixel][25]

    const int b = blockIdx.y;
    const int ti0 = (blockIdx.x >> 3) << 4;
    const int tj0 = (blockIdx.x & 7) << 4;
    const int tid = threadIdx.x;
    const int sy0 = (ti0 >> 1) - 2;
    const int sx0 = (tj0 >> 1) - 2;

    // stage x window, position-major (gmem coalesced; smem writes 4-way)
#pragma unroll 4
    for (int it = 0; it < 72; it++) {
        int idx = tid + it * 256;            // idx = c*144 + pos
        int c = idx / 144;
        int pos = idx - c * 144;
        int yy = pos / 12;
        int xx = pos - yy * 12;
        int gy = sy0 + yy, gx = sx0 + xx;
        float v = 0.f;
        if ((unsigned)gy < 64u && (unsigned)gx < 64u)
            v = x[((size_t)(b * CIN + c) << 12) + (gy << 6) + gx];
        srcs[pos * CS + c] = v;
    }

    // softmax weights for this thread's pixel
    {
        int py = tid >> 4, px = tid & 15;
        int gi = ti0 + py, gj = tj0 + px;
        int y0 = gi >> 1, x0 = gj >> 1;
        int sub = ((gi & 1) << 1) | (gj & 1);
        float l[25];
        float mx = -1e30f;
#pragma unroll
        for (int k = 0; k < 25; k++) {
            int ch = (k << 2) + sub;
            float v = fmaf(g_t2[((size_t)(b * OC2 + ch) << 12) + (y0 << 6) + x0],
                           g_sc2[ch], g_sh2[ch]);
            l[k] = v;
            mx = fmaxf(mx, v);
        }
        float s = 0.f;
#pragma unroll
        for (int k = 0; k < 25; k++) { l[k] = expf(l[k] - mx); s += l[k]; }
        float inv = 1.f / s;
#pragma unroll
        for (int k = 0; k < 25; k++) wgt[tid * 25 + k] = l[k] * inv;
    }
    __syncthreads();

    const int cg = tid & 1;
    const int qx = (tid >> 1) & 7;
    const int i = tid >> 4;

    u64 W0[25], W1[25];
    {
        const float* wp = &wgt[(i * 16 + 2 * qx) * 25];
#pragma unroll
        for (int k = 0; k < 25; k++) {
            float a = wp[k], bb = wp[25 + k];
            W0[k] = pk(a, a);
            W1[k] = pk(bb, bb);
        }
    }

    const int posbase = (i >> 1) * 12 + qx;
    const int gi = ti0 + i;
    const int gj = tj0 + 2 * qx;
    const u64* S = (const u64*)srcs;

#pragma unroll 2
    for (int t = 0; t < 32; t++) {
        int c = 4 * t + 2 * cg;            // channel pair (c, c+1)
        int cb = c >> 1;
        u64 a0 = 0ull, a1 = 0ull;
#pragma unroll
        for (int dy = 0; dy < 5; dy++) {
            const u64* r = S + (posbase + dy * 12) * (CS / 2) + cb;
#pragma unroll
            for (int dx = 0; dx < 5; dx++) {
                u64 sv = r[dx * (CS / 2)];
                fma2(a0, W0[5 * dy + dx], sv);
                fma2(a1, W1[5 * dy + dx], sv);
            }
        }
        float e0, h0, e1, h1;
        unpk(a0, e0, h0);     // (chan c, c+1) at pixel gj
        unpk(a1, e1, h1);     // (chan c, c+1) at pixel gj+1
        size_t ob = (((size_t)(b * CIN + c) << 7) + gi) * 128 + gj;
        *(float2*)&out[ob] = make_float2(e0, e1);
        *(float2*)&out[ob + 16384] = make_float2(h0, h1);
    }
}

// ---------------------------------------------------------------------------
extern "C" void kernel_launch(void* const* d_in, const int* in_sizes, int n_in,
                              void* d_out, int out_size) {
    const float* x      = (const float*)d_in[0];
    const float* comp_w = (const float*)d_in[1];
    const float* comp_g = (const float*)d_in[2];
    const float* comp_b = (const float*)d_in[3];
    const float* enc_w  = (const float*)d_in[4];
    const float* enc_g  = (const float*)d_in[5];
    const float* enc_b  = (const float*)d_in[6];
    float* out = (float*)d_out;

    cudaFuncSetAttribute(k_conv3, cudaFuncAttributeMaxDynamicSharedMemorySize, CONV3_SMEM);
    cudaFuncSetAttribute(k_reasm, cudaFuncAttributeMaxDynamicSharedMemorySize, REASM_SMEM);

    k_conv1<<<dim3(16, B), 256>>>(x, comp_w);
    k_fin1<<<MID, 128>>>(comp_g, comp_b);
    k_conv3<<<dim3(32, B), 256, CONV3_SMEM>>>(enc_w);
    k_fin2<<<OC2, 256>>>(enc_g, enc_b);
    k_reasm<<<dim3(64, B), 256, REASM_SMEM>>>(x, out);
}

// round 5
// speedup vs baseline: 1.3086x; 1.2460x over previous
#include <cuda_runtime.h>
#include <cstdint>
#include <math.h>

// ---------------------------------------------------------------------------
// CARAFE fp32: conv1x1+BN+SiLU -> conv3x3+BN -> pxshuffle(2) -> softmax(25)
//              -> 5x5 dil-2 content-aware reassembly.  x[8,128,64,64]
// Round 5: R4 + restored wsm overread pad (the R4 fault) + aligned globals.
// ---------------------------------------------------------------------------

#define B 8
#define CIN 128
#define MID 64
#define OC2 100
#define HW 4096
#define EPS 1e-5f

typedef unsigned long long u64;

__device__ __forceinline__ u64 pk(float lo, float hi) {
    u64 r; asm("mov.b64 %0,{%1,%2};" : "=l"(r) : "f"(lo), "f"(hi)); return r;
}
__device__ __forceinline__ void fma2(u64& d, u64 a, u64 b) {
    asm("fma.rn.f32x2 %0,%1,%2,%0;" : "+l"(d) : "l"(a), "l"(b));
}
__device__ __forceinline__ u64 add2(u64 a, u64 b) {
    u64 r; asm("add.rn.f32x2 %0,%1,%2;" : "=l"(r) : "l"(a), "l"(b)); return r;
}
__device__ __forceinline__ void unpk(u64 a, float& lo, float& hi) {
    asm("mov.b64 {%0,%1},%2;" : "=f"(lo), "=f"(hi) : "l"(a));
}

// scratch (16B-aligned: accessed through float4/u64 casts)
__device__ __align__(16) float g_t1[B * MID * HW];
__device__ __align__(16) float g_t2[B * OC2 * HW];
__device__ float g_sc1[MID], g_sh1[MID];
__device__ float g_sc2[OC2], g_sh2[OC2];
__device__ __align__(16) float g_p1s[128 * 64], g_p1q[128 * 64];
__device__ __align__(16) float g_p2s[256 * 100], g_p2q[256 * 100];
__device__ __align__(16) float g_w3T[576 * 100];   // [(cc*9+t)][oc]
__device__ __align__(16) float g_w1T[128 * 64];    // [cc][oc]

__device__ __forceinline__ void wred2(u64& s, u64& q) {
#pragma unroll
    for (int o = 16; o; o >>= 1) {
        s = add2(s, __shfl_down_sync(0xFFFFFFFFu, s, o));
        q = add2(q, __shfl_down_sync(0xFFFFFFFFu, q, o));
    }
}

// ---------------------------------------------------------------------------
// prep: transpose weights into oc-fast layouts
// ---------------------------------------------------------------------------
__global__ void k_prep(const float* __restrict__ cw, const float* __restrict__ ew) {
    int idx = blockIdx.x * 256 + threadIdx.x;
    if (idx < 57600) {
        int ct = idx / 100, oc = idx - ct * 100;   // ct = cc*9+t
        int cc = ct / 9, t = ct - cc * 9;
        g_w3T[idx] = ew[(oc * 64 + cc) * 9 + t];
    } else if (idx < 57600 + 8192) {
        int j = idx - 57600;
        int cc = j >> 6, oc = j & 63;
        g_w1T[j] = cw[oc * 128 + cc];
    }
}

// ---------------------------------------------------------------------------
// conv1x1: grid(16,8) x 256.  thread: 4 pixels x 8 oc-pairs. + BN partials.
// ---------------------------------------------------------------------------
__global__ void k_conv1(const float* __restrict__ x) {
    __shared__ float xs[32][256];
    __shared__ __align__(16) float ws1[32][64];
    __shared__ u64 r_s[8][8], r_q[8][8];
    const int b = blockIdx.y;
    const int p0 = blockIdx.x * 256;
    const int tid = threadIdx.x;
    const int pixg = tid & 63;
    const int ocg = tid >> 6;

    u64 acc[8][4];
#pragma unroll
    for (int p = 0; p < 8; p++)
#pragma unroll
        for (int j = 0; j < 4; j++) acc[p][j] = 0ull;

    for (int c0 = 0; c0 < CIN; c0 += 32) {
        __syncthreads();
#pragma unroll 4
        for (int j = 0; j < 32; j++)
            xs[j][tid] = x[((size_t)(b * CIN + c0 + j) << 12) + p0 + tid];
#pragma unroll
        for (int j = 0; j < 8; j++) {
            int idx = j * 256 + tid;
            int oc = idx & 63, cc = idx >> 6;
            ws1[cc][oc] = g_w1T[(c0 + cc) * 64 + oc];   // coalesced
        }
        __syncthreads();
#pragma unroll 4
        for (int cc = 0; cc < 32; cc++) {
            float4 xv = *(const float4*)&xs[cc][pixg * 4];
            u64 P0 = pk(xv.x, xv.x), P1 = pk(xv.y, xv.y);
            u64 P2 = pk(xv.z, xv.z), P3 = pk(xv.w, xv.w);
            const u64* wp = (const u64*)&ws1[cc][ocg * 16];
#pragma unroll
            for (int p = 0; p < 8; p++) {
                u64 w = wp[p];
                fma2(acc[p][0], w, P0);
                fma2(acc[p][1], w, P1);
                fma2(acc[p][2], w, P2);
                fma2(acc[p][3], w, P3);
            }
        }
    }
    const int lane = tid & 31, wid = tid >> 5;
#pragma unroll
    for (int p = 0; p < 8; p++) {
        int oce = ocg * 16 + 2 * p;
        float e0, o0, e1, o1, e2, o2, e3, o3;
        unpk(acc[p][0], e0, o0); unpk(acc[p][1], e1, o1);
        unpk(acc[p][2], e2, o2); unpk(acc[p][3], e3, o3);
        *(float4*)&g_t1[((size_t)(b * MID + oce) << 12) + p0 + pixg * 4] =
            make_float4(e0, e1, e2, e3);
        *(float4*)&g_t1[((size_t)(b * MID + oce + 1) << 12) + p0 + pixg * 4] =
            make_float4(o0, o1, o2, o3);
        u64 s = add2(add2(acc[p][0], acc[p][1]), add2(acc[p][2], acc[p][3]));
        u64 q = 0ull;
        fma2(q, acc[p][0], acc[p][0]); fma2(q, acc[p][1], acc[p][1]);
        fma2(q, acc[p][2], acc[p][2]); fma2(q, acc[p][3], acc[p][3]);
        wred2(s, q);
        if (lane == 0) { r_s[wid][p] = s; r_q[wid][p] = q; }
    }
    __syncthreads();
    if (tid < 32) {
        int g = tid >> 3, p = tid & 7;
        u64 s = add2(r_s[2 * g][p], r_s[2 * g + 1][p]);
        u64 q = add2(r_q[2 * g][p], r_q[2 * g + 1][p]);
        int blk = b * 16 + blockIdx.x;
        *(u64*)&g_p1s[blk * 64 + 2 * (g * 8 + p)] = s;
        *(u64*)&g_p1q[blk * 64 + 2 * (g * 8 + p)] = q;
    }
}

// ---------------------------------------------------------------------------
// finalize BN1 / BN2
// ---------------------------------------------------------------------------
__global__ void k_fin1(const float* __restrict__ gam, const float* __restrict__ bet) {
    const int oc = blockIdx.x, t = threadIdx.x;
    float s = g_p1s[t * 64 + oc], q = g_p1q[t * 64 + oc];
#pragma unroll
    for (int o = 16; o; o >>= 1) {
        s += __shfl_down_sync(0xFFFFFFFFu, s, o);
        q += __shfl_down_sync(0xFFFFFFFFu, q, o);
    }
    __shared__ float ss[4], qq[4];
    if ((t & 31) == 0) { ss[t >> 5] = s; qq[t >> 5] = q; }
    __syncthreads();
    if (t == 0) {
        s = ss[0] + ss[1] + ss[2] + ss[3];
        q = qq[0] + qq[1] + qq[2] + qq[3];
        const float inv = 1.f / 32768.f;
        float m = s * inv, var = fmaf(-m, m, q * inv);
        float k = gam[oc] * rsqrtf(var + EPS);
        g_sc1[oc] = k; g_sh1[oc] = bet[oc] - m * k;
    }
}
__global__ void k_fin2(const float* __restrict__ gam, const float* __restrict__ bet) {
    const int oc = blockIdx.x, t = threadIdx.x;
    float s = g_p2s[t * 100 + oc], q = g_p2q[t * 100 + oc];
#pragma unroll
    for (int o = 16; o; o >>= 1) {
        s += __shfl_down_sync(0xFFFFFFFFu, s, o);
        q += __shfl_down_sync(0xFFFFFFFFu, q, o);
    }
    __shared__ float ss[8], qq[8];
    if ((t & 31) == 0) { ss[t >> 5] = s; qq[t >> 5] = q; }
    __syncthreads();
    if (t == 0) {
        s = 0.f; q = 0.f;
#pragma unroll
        for (int i = 0; i < 8; i++) { s += ss[i]; q += qq[i]; }
        const float inv = 1.f / 32768.f;
        float m = s * inv, var = fmaf(-m, m, q * inv);
        float k = gam[oc] * rsqrtf(var + EPS);
        g_sc2[oc] = k; g_sh2[oc] = bet[oc] - m * k;
    }
}

// ---------------------------------------------------------------------------
// conv3x3 (pad 1) on silu(bn(t1)) -> t2.  grid(32,8) x 256.
// inb row stride 19; weight staging = contiguous float4 copy.
// smem: inb[16][10][19] + wsm[144][100] + 16-float pad (compute loop
// overreads wsm by up to 12 floats for the guarded-out oc>=100 lanes).
// ---------------------------------------------------------------------------
#define CONV3_SMEM ((3040 + 14400 + 16) * 4)

__global__ __launch_bounds__(256, 2) void k_conv3() {
    extern __shared__ float sm[];
    float* inb = sm;            // [cc][10][19]
    float* wsm = sm + 3040;     // [(cc*9+t)][100] oc-fast

    const int b = blockIdx.y;
    const int ox0 = (blockIdx.x & 3) * 16;
    const int oy0 = (blockIdx.x >> 2) * 8;
    const int tid = threadIdx.x;
    const int pixg = tid & 31;
    const int ocg = tid >> 5;
    const int py = pixg >> 2;
    const int pxb = (pixg & 3) * 4;

    u64 acc[7][4];
#pragma unroll
    for (int k = 0; k < 7; k++)
#pragma unroll
        for (int j = 0; j < 4; j++) acc[k][j] = 0ull;

    for (int c0 = 0; c0 < MID; c0 += 16) {
        __syncthreads();
        // input tile with BN+SiLU (row stride 19)
        for (int idx = tid; idx < 3040; idx += 256) {
            int cc = idx / 190;
            int r = idx - cc * 190;
            int y = r / 19;
            int xx = r - y * 19;
            int gy = oy0 - 1 + y, gx = ox0 - 1 + xx;
            float v = 0.f;
            if ((unsigned)gy < 64u && (unsigned)gx < 64u && xx < 18) {
                int c = c0 + cc;
                float raw = g_t1[((size_t)(b * MID + c) << 12) + (gy << 6) + gx];
                float z = fmaf(raw, g_sc1[c], g_sh1[c]);
                v = z / (1.f + expf(-z));
            }
            inb[idx] = v;
        }
        // weights: contiguous float4 copy from pre-transposed g_w3T
        {
            const float4* src = (const float4*)&g_w3T[c0 * 900];
            float4* dst = (float4*)wsm;
            for (int idx = tid; idx < 3600; idx += 256) dst[idx] = src[idx];
        }
        __syncthreads();

#pragma unroll 1
        for (int cc = 0; cc < 16; cc++) {
            const float* rb = inb + cc * 190 + pxb;
#pragma unroll
            for (int ky = 0; ky < 3; ky++) {
                const float* rp = rb + (py + ky) * 19;
                float v0 = rp[0], v1 = rp[1], v2 = rp[2],
                      v3 = rp[3], v4 = rp[4], v5 = rp[5];
                u64 P[6];
                P[0] = pk(v0, v0); P[1] = pk(v1, v1); P[2] = pk(v2, v2);
                P[3] = pk(v3, v3); P[4] = pk(v4, v4); P[5] = pk(v5, v5);
#pragma unroll
                for (int kx = 0; kx < 3; kx++) {
                    const u64* wrow =
                        (const u64*)(wsm + (cc * 9 + ky * 3 + kx) * 100) + ocg;
#pragma unroll
                    for (int k = 0; k < 7; k++) {
                        u64 w = wrow[k * 8];
                        fma2(acc[k][0], w, P[kx]);
                        fma2(acc[k][1], w, P[kx + 1]);
                        fma2(acc[k][2], w, P[kx + 2]);
                        fma2(acc[k][3], w, P[kx + 3]);
                    }
                }
            }
        }
    }

    const int lane = tid & 31;
    const int blk = b * 32 + blockIdx.x;
#pragma unroll
    for (int k = 0; k < 7; k++) {
        bool valid = (k < 6) || (ocg < 2);
        if (!valid) continue;
        int oce = 2 * (ocg + 8 * k);
        float e0, o0, e1, o1, e2, o2, e3, o3;
        unpk(acc[k][0], e0, o0); unpk(acc[k][1], e1, o1);
        unpk(acc[k][2], e2, o2); unpk(acc[k][3], e3, o3);
        size_t ob = ((size_t)(b * OC2 + oce) << 12) + ((oy0 + py) << 6) + ox0 + pxb;
        *(float4*)&g_t2[ob] = make_float4(e0, e1, e2, e3);
        *(float4*)&g_t2[ob + HW] = make_float4(o0, o1, o2, o3);
        u64 s = add2(add2(acc[k][0], acc[k][1]), add2(acc[k][2], acc[k][3]));
        u64 q = 0ull;
        fma2(q, acc[k][0], acc[k][0]); fma2(q, acc[k][1], acc[k][1]);
        fma2(q, acc[k][2], acc[k][2]); fma2(q, acc[k][3], acc[k][3]);
        wred2(s, q);
        if (lane == 0) {
            *(u64*)&g_p2s[blk * 100 + oce] = s;
            *(u64*)&g_p2q[blk * 100 + oce] = q;
        }
    }
}

// ---------------------------------------------------------------------------
// reassembly: grid(64,8) x 256. thread = pixel-pair x channel-half,
// channels in 4 groups of 8 pairs (16 u64 accs live).
// ---------------------------------------------------------------------------
#define CS 132
#define REASM_SMEM ((144 * CS + 256 * 25) * 4)

__global__ __launch_bounds__(256, 2) void k_reasm(const float* __restrict__ x,
                                                  float* __restrict__ out) {
    extern __shared__ float sm[];
    float* srcs = sm;                 // [pos 144][CS]
    float* wgt = sm + 144 * CS;       // [pixel 256][25]

    const int b = blockIdx.y;
    const int ti0 = (blockIdx.x >> 3) << 4;
    const int tj0 = (blockIdx.x & 7) << 4;
    const int tid = threadIdx.x;
    const int sy0 = (ti0 >> 1) - 2;
    const int sx0 = (tj0 >> 1) - 2;

#pragma unroll 4
    for (int it = 0; it < 72; it++) {
        int idx = tid + it * 256;            // idx = c*144 + pos
        int c = idx / 144;
        int pos = idx - c * 144;
        int yy = pos / 12;
        int xx = pos - yy * 12;
        int gy = sy0 + yy, gx = sx0 + xx;
        float v = 0.f;
        if ((unsigned)gy < 64u && (unsigned)gx < 64u)
            v = x[((size_t)(b * CIN + c) << 12) + (gy << 6) + gx];
        srcs[pos * CS + c] = v;
    }

    {
        int py = tid >> 4, px = tid & 15;
        int gi = ti0 + py, gj = tj0 + px;
        int y0 = gi >> 1, x0 = gj >> 1;
        int sub = ((gi & 1) << 1) | (gj & 1);
        float l[25];
        float mx = -1e30f;
#pragma unroll
        for (int k = 0; k < 25; k++) {
            int ch = (k << 2) + sub;
            float v = fmaf(g_t2[((size_t)(b * OC2 + ch) << 12) + (y0 << 6) + x0],
                           g_sc2[ch], g_sh2[ch]);
            l[k] = v;
            mx = fmaxf(mx, v);
        }
        float s = 0.f;
#pragma unroll
        for (int k = 0; k < 25; k++) { l[k] = expf(l[k] - mx); s += l[k]; }
        float inv = 1.f / s;
#pragma unroll
        for (int k = 0; k < 25; k++) wgt[tid * 25 + k] = l[k] * inv;
    }
    __syncthreads();

    const int cg = tid & 1;
    const int qx = (tid >> 1) & 7;
    const int i = tid >> 4;
    const int posbase = (i >> 1) * 12 + qx;
    const int gi = ti0 + i;
    const int gj = tj0 + 2 * qx;
    const u64* S = (const u64*)srcs;
    const float* wp = &wgt[(i * 16 + 2 * qx) * 25];

#pragma unroll 1
    for (int g = 0; g < 4; g++) {
        u64 a0[8], a1[8];
#pragma unroll
        for (int j = 0; j < 8; j++) { a0[j] = 0ull; a1[j] = 0ull; }
#pragma unroll
        for (int dy = 0; dy < 5; dy++) {
#pragma unroll
            for (int dx = 0; dx < 5; dx++) {
                int k = dy * 5 + dx;
                float w0s = wp[k], w1s = wp[25 + k];
                u64 W0 = pk(w0s, w0s), W1 = pk(w1s, w1s);
                const u64* r = S + (posbase + dy * 12 + dx) * (CS / 2) + g * 16 + cg;
#pragma unroll
                for (int j = 0; j < 8; j++) {
                    u64 sv = r[2 * j];
                    fma2(a0[j], W0, sv);
                    fma2(a1[j], W1, sv);
                }
            }
        }
#pragma unroll
        for (int j = 0; j < 8; j++) {
            int c = 4 * (g * 8 + j) + 2 * cg;
            float e0, h0, e1, h1;
            unpk(a0[j], e0, h0);
            unpk(a1[j], e1, h1);
            size_t ob = (((size_t)(b * CIN + c) << 7) + gi) * 128 + gj;
            *(float2*)&out[ob] = make_float2(e0, e1);
            *(float2*)&out[ob + 16384] = make_float2(h0, h1);
        }
    }
}

// ---------------------------------------------------------------------------
extern "C" void kernel_launch(void* const* d_in, const int* in_sizes, int n_in,
                              void* d_out, int out_size) {
    const float* x      = (const float*)d_in[0];
    const float* comp_w = (const float*)d_in[1];
    const float* comp_g = (const float*)d_in[2];
    const float* comp_b = (const float*)d_in[3];
    const float* enc_w  = (const float*)d_in[4];
    const float* enc_g  = (const float*)d_in[5];
    const float* enc_b  = (const float*)d_in[6];
    float* out = (float*)d_out;

    cudaFuncSetAttribute(k_conv3, cudaFuncAttributeMaxDynamicSharedMemorySize, CONV3_SMEM);
    cudaFuncSetAttribute(k_reasm, cudaFuncAttributeMaxDynamicSharedMemorySize, REASM_SMEM);

    k_prep<<<257, 256>>>(comp_w, enc_w);                 // 0
    k_conv1<<<dim3(16, B), 256>>>(x);                    // 1
    k_fin1<<<MID, 128>>>(comp_g, comp_b);                // 2
    k_conv3<<<dim3(32, B), 256, CONV3_SMEM>>>();         // 3  <- ncu slot
    k_fin2<<<OC2, 256>>>(enc_g, enc_b);                  // 4
    k_reasm<<<dim3(64, B), 256, REASM_SMEM>>>(x, out);   // 5
}

// round 7
// speedup vs baseline: 1.3096x; 1.0008x over previous
#include <cuda_runtime.h>
#include <cstdint>
#include <math.h>

// ---------------------------------------------------------------------------
// CARAFE fp32.  Round 6: conv3 LDS.128 weight layout (per-warp contiguous
// oc-pairs), stride-20 aligned input rows; reassembly 2x2-quad threads with
// LDS.128 channel reads (8 fma2 per load).
// ---------------------------------------------------------------------------

#define B 8
#define CIN 128
#define MID 64
#define OC2 100
#define HW 4096
#define EPS 1e-5f

typedef unsigned long long u64;

__device__ __forceinline__ u64 pk(float lo, float hi) {
    u64 r; asm("mov.b64 %0,{%1,%2};" : "=l"(r) : "f"(lo), "f"(hi)); return r;
}
__device__ __forceinline__ void fma2(u64& d, u64 a, u64 b) {
    asm("fma.rn.f32x2 %0,%1,%2,%0;" : "+l"(d) : "l"(a), "l"(b));
}
__device__ __forceinline__ u64 add2(u64 a, u64 b) {
    u64 r; asm("add.rn.f32x2 %0,%1,%2;" : "=l"(r) : "l"(a), "l"(b)); return r;
}
__device__ __forceinline__ void unpk(u64 a, float& lo, float& hi) {
    asm("mov.b64 {%0,%1},%2;" : "=f"(lo), "=f"(hi) : "l"(a));
}

// scratch (16B-aligned)
__device__ __align__(16) float g_t1[B * MID * HW];
__device__ __align__(16) float g_t2[B * OC2 * HW];
__device__ float g_sc1[MID], g_sh1[MID];
__device__ float g_sc2[OC2], g_sh2[OC2];
__device__ __align__(16) float g_p1s[128 * 64], g_p1q[128 * 64];
__device__ __align__(16) float g_p2s[256 * 100], g_p2q[256 * 100];
__device__ __align__(16) float g_w3T[576 * 128];   // [ct][128]: warp ocg slots 16*ocg..+15
__device__ __align__(16) float g_w1T[128 * 64];    // [cc][oc]

__device__ __forceinline__ void wred2(u64& s, u64& q) {
#pragma unroll
    for (int o = 16; o; o >>= 1) {
        s = add2(s, __shfl_down_sync(0xFFFFFFFFu, s, o));
        q = add2(q, __shfl_down_sync(0xFFFFFFFFu, q, o));
    }
}

// ---------------------------------------------------------------------------
// prep: weight layouts.  conv3: slot = 16*ocg + 2*kp + e -> oc = 14*ocg+2*kp+e
// ---------------------------------------------------------------------------
__global__ void k_prep(const float* __restrict__ cw, const float* __restrict__ ew) {
    int idx = blockIdx.x * 256 + threadIdx.x;
    if (idx < 576 * 128) {
        int ct = idx >> 7, slot = idx & 127;
        int cc = ct / 9, t = ct - cc * 9;
        int ocg = slot >> 4, r = slot & 15;
        int kp = r >> 1, e = r & 1;
        int oc = 14 * ocg + 2 * kp + e;
        float v = 0.f;
        if (kp < 7 && oc < 100) v = ew[(oc * 64 + cc) * 9 + t];
        g_w3T[idx] = v;
    } else if (idx < 576 * 128 + 8192) {
        int j = idx - 576 * 128;
        int cc = j >> 6, oc = j & 63;
        g_w1T[j] = cw[oc * 128 + cc];
    }
}

// ---------------------------------------------------------------------------
// conv1x1: grid(16,8) x 256.  thread: 4 px x 8 oc-pairs. + BN partials.
// ---------------------------------------------------------------------------
__global__ void k_conv1(const float* __restrict__ x) {
    __shared__ float xs[32][256];
    __shared__ __align__(16) float ws1[32][64];
    __shared__ u64 r_s[8][8], r_q[8][8];
    const int b = blockIdx.y;
    const int p0 = blockIdx.x * 256;
    const int tid = threadIdx.x;
    const int pixg = tid & 63;
    const int ocg = tid >> 6;

    u64 acc[8][4];
#pragma unroll
    for (int p = 0; p < 8; p++)
#pragma unroll
        for (int j = 0; j < 4; j++) acc[p][j] = 0ull;

    for (int c0 = 0; c0 < CIN; c0 += 32) {
        __syncthreads();
#pragma unroll 4
        for (int j = 0; j < 32; j++)
            xs[j][tid] = x[((size_t)(b * CIN + c0 + j) << 12) + p0 + tid];
#pragma unroll
        for (int j = 0; j < 8; j++) {
            int idx = j * 256 + tid;
            int oc = idx & 63, cc = idx >> 6;
            ws1[cc][oc] = g_w1T[(c0 + cc) * 64 + oc];
        }
        __syncthreads();
#pragma unroll 4
        for (int cc = 0; cc < 32; cc++) {
            float4 xv = *(const float4*)&xs[cc][pixg * 4];
            u64 P0 = pk(xv.x, xv.x), P1 = pk(xv.y, xv.y);
            u64 P2 = pk(xv.z, xv.z), P3 = pk(xv.w, xv.w);
            const u64* wp = (const u64*)&ws1[cc][ocg * 16];
#pragma unroll
            for (int p = 0; p < 8; p++) {
                u64 w = wp[p];
                fma2(acc[p][0], w, P0);
                fma2(acc[p][1], w, P1);
                fma2(acc[p][2], w, P2);
                fma2(acc[p][3], w, P3);
            }
        }
    }
    const int lane = tid & 31, wid = tid >> 5;
#pragma unroll
    for (int p = 0; p < 8; p++) {
        int oce = ocg * 16 + 2 * p;
        float e0, o0, e1, o1, e2, o2, e3, o3;
        unpk(acc[p][0], e0, o0); unpk(acc[p][1], e1, o1);
        unpk(acc[p][2], e2, o2); unpk(acc[p][3], e3, o3);
        *(float4*)&g_t1[((size_t)(b * MID + oce) << 12) + p0 + pixg * 4] =
            make_float4(e0, e1, e2, e3);
        *(float4*)&g_t1[((size_t)(b * MID + oce + 1) << 12) + p0 + pixg * 4] =
            make_float4(o0, o1, o2, o3);
        u64 s = add2(add2(acc[p][0], acc[p][1]), add2(acc[p][2], acc[p][3]));
        u64 q = 0ull;
        fma2(q, acc[p][0], acc[p][0]); fma2(q, acc[p][1], acc[p][1]);
        fma2(q, acc[p][2], acc[p][2]); fma2(q, acc[p][3], acc[p][3]);
        wred2(s, q);
        if (lane == 0) { r_s[wid][p] = s; r_q[wid][p] = q; }
    }
    __syncthreads();
    if (tid < 32) {
        int g = tid >> 3, p = tid & 7;
        u64 s = add2(r_s[2 * g][p], r_s[2 * g + 1][p]);
        u64 q = add2(r_q[2 * g][p], r_q[2 * g + 1][p]);
        int blk = b * 16 + blockIdx.x;
        *(u64*)&g_p1s[blk * 64 + 2 * (g * 8 + p)] = s;
        *(u64*)&g_p1q[blk * 64 + 2 * (g * 8 + p)] = q;
    }
}

// ---------------------------------------------------------------------------
// finalize BN1 / BN2
// ---------------------------------------------------------------------------
__global__ void k_fin1(const float* __restrict__ gam, const float* __restrict__ bet) {
    const int oc = blockIdx.x, t = threadIdx.x;
    float s = g_p1s[t * 64 + oc], q = g_p1q[t * 64 + oc];
#pragma unroll
    for (int o = 16; o; o >>= 1) {
        s += __shfl_down_sync(0xFFFFFFFFu, s, o);
        q += __shfl_down_sync(0xFFFFFFFFu, q, o);
    }
    __shared__ float ss[4], qq[4];
    if ((t & 31) == 0) { ss[t >> 5] = s; qq[t >> 5] = q; }
    __syncthreads();
    if (t == 0) {
        s = ss[0] + ss[1] + ss[2] + ss[3];
        q = qq[0] + qq[1] + qq[2] + qq[3];
        const float inv = 1.f / 32768.f;
        float m = s * inv, var = fmaf(-m, m, q * inv);
        float k = gam[oc] * rsqrtf(var + EPS);
        g_sc1[oc] = k; g_sh1[oc] = bet[oc] - m * k;
    }
}
__global__ void k_fin2(const float* __restrict__ gam, const float* __restrict__ bet) {
    const int oc = blockIdx.x, t = threadIdx.x;
    float s = g_p2s[t * 100 + oc], q = g_p2q[t * 100 + oc];
#pragma unroll
    for (int o = 16; o; o >>= 1) {
        s += __shfl_down_sync(0xFFFFFFFFu, s, o);
        q += __shfl_down_sync(0xFFFFFFFFu, q, o);
    }
    __shared__ float ss[8], qq[8];
    if ((t & 31) == 0) { ss[t >> 5] = s; qq[t >> 5] = q; }
    __syncthreads();
    if (t == 0) {
        s = 0.f; q = 0.f;
#pragma unroll
        for (int i = 0; i < 8; i++) { s += ss[i]; q += qq[i]; }
        const float inv = 1.f / 32768.f;
        float m = s * inv, var = fmaf(-m, m, q * inv);
        float k = gam[oc] * rsqrtf(var + EPS);
        g_sc2[oc] = k; g_sh2[oc] = bet[oc] - m * k;
    }
}

// ---------------------------------------------------------------------------
// conv3x3: grid(32,8) x 256.  Warp ocg owns oc-pairs 7*ocg..+6 (contiguous,
// padded to 8 in smem -> 4x LDS.128 per (cc,ky,kx)).  Input rows stride 20
// (16B-aligned -> LDS.128+LDS.64).
// smem: inb[16][10][20]=3200 + wsm[144][128]=18432 (+pad)
// ---------------------------------------------------------------------------
#define CONV3_SMEM ((3200 + 18432 + 16) * 4)

__global__ __launch_bounds__(256, 2) void k_conv3() {
    extern __shared__ float sm[];
    float* inb = sm;            // [cc][10][20]
    float* wsm = sm + 3200;     // [ct][128]

    const int b = blockIdx.y;
    const int ox0 = (blockIdx.x & 3) * 16;
    const int oy0 = (blockIdx.x >> 2) * 8;
    const int tid = threadIdx.x;
    const int pixg = tid & 31;
    const int ocg = tid >> 5;
    const int py = pixg >> 2;
    const int pxb = (pixg & 3) * 4;

    u64 acc[7][4];
#pragma unroll
    for (int k = 0; k < 7; k++)
#pragma unroll
        for (int j = 0; j < 4; j++) acc[k][j] = 0ull;

    for (int c0 = 0; c0 < MID; c0 += 16) {
        __syncthreads();
        // input tile with BN+SiLU (row stride 20; cols 18,19 unused)
        for (int idx = tid; idx < 3200; idx += 256) {
            int cc = idx / 200;
            int r = idx - cc * 200;
            int y = r / 20;
            int xx = r - y * 20;
            int gy = oy0 - 1 + y, gx = ox0 - 1 + xx;
            float v = 0.f;
            if ((unsigned)gy < 64u && (unsigned)gx < 64u && xx < 18) {
                int c = c0 + cc;
                float raw = g_t1[((size_t)(b * MID + c) << 12) + (gy << 6) + gx];
                float z = fmaf(raw, g_sc1[c], g_sh1[c]);
                v = z / (1.f + expf(-z));
            }
            inb[idx] = v;
        }
        // weights: contiguous float4 copy of 144 rows x 128
        {
            const float4* src = (const float4*)&g_w3T[c0 * 9 * 128];
            float4* dst = (float4*)wsm;
            for (int idx = tid; idx < 4608; idx += 256) dst[idx] = src[idx];
        }
        __syncthreads();

#pragma unroll 1
        for (int cc = 0; cc < 16; cc++) {
            const float* rb = inb + cc * 200 + pxb;
#pragma unroll
            for (int ky = 0; ky < 3; ky++) {
                const float* rp = rb + (py + ky) * 20;
                float4 vA = *(const float4*)rp;
                float2 vB = *(const float2*)(rp + 4);
                u64 P[6];
                P[0] = pk(vA.x, vA.x); P[1] = pk(vA.y, vA.y);
                P[2] = pk(vA.z, vA.z); P[3] = pk(vA.w, vA.w);
                P[4] = pk(vB.x, vB.x); P[5] = pk(vB.y, vB.y);
#pragma unroll
                for (int kx = 0; kx < 3; kx++) {
                    const ulonglong2* wq =
                        (const ulonglong2*)(wsm + (cc * 9 + ky * 3 + kx) * 128) + ocg * 4;
                    ulonglong2 q0 = wq[0], q1 = wq[1], q2 = wq[2], q3 = wq[3];
                    u64 w[7] = {q0.x, q0.y, q1.x, q1.y, q2.x, q2.y, q3.x};
#pragma unroll
                    for (int k = 0; k < 7; k++) {
                        fma2(acc[k][0], w[k], P[kx]);
                        fma2(acc[k][1], w[k], P[kx + 1]);
                        fma2(acc[k][2], w[k], P[kx + 2]);
                        fma2(acc[k][3], w[k], P[kx + 3]);
                    }
                }
            }
        }
    }

    const int lane = tid & 31;
    const int blk = b * 32 + blockIdx.x;
#pragma unroll
    for (int k = 0; k < 7; k++) {
        int pr = 7 * ocg + k;              // oc pair index
        if (pr >= 50) continue;            // warp-uniform guard
        int oce = 2 * pr;
        float e0, o0, e1, o1, e2, o2, e3, o3;
        unpk(acc[k][0], e0, o0); unpk(acc[k][1], e1, o1);
        unpk(acc[k][2], e2, o2); unpk(acc[k][3], e3, o3);
        size_t ob = ((size_t)(b * OC2 + oce) << 12) + ((oy0 + py) << 6) + ox0 + pxb;
        *(float4*)&g_t2[ob] = make_float4(e0, e1, e2, e3);
        *(float4*)&g_t2[ob + HW] = make_float4(o0, o1, o2, o3);
        u64 s = add2(add2(acc[k][0], acc[k][1]), add2(acc[k][2], acc[k][3]));
        u64 q = 0ull;
        fma2(q, acc[k][0], acc[k][0]); fma2(q, acc[k][1], acc[k][1]);
        fma2(q, acc[k][2], acc[k][2]); fma2(q, acc[k][3], acc[k][3]);
        wred2(s, q);
        if (lane == 0) {
            *(u64*)&g_p2s[blk * 100 + oce] = s;
            *(u64*)&g_p2q[blk * 100 + oce] = q;
        }
    }
}

// ---------------------------------------------------------------------------
// reassembly: grid(64,8) x 256.  Thread = 2x2 output quad x 1/4 channels.
// srcs layout: [pos 144][4 subsets x (16 pairs + 1 pad u64)] stride 140 floats
//   pair p at u64 = pos*70 + (p>>4)*18 + (p&15)   (16B-aligned groups)
// Each LDS.128 (2 ch-pairs) feeds 8 fma2 (4 quad pixels x 2 pairs).
// ---------------------------------------------------------------------------
#define RPOS 140
#define REASM_SMEM ((144 * RPOS + 256 * 25) * 4)

__global__ __launch_bounds__(256, 2) void k_reasm(const float* __restrict__ x,
                                                  float* __restrict__ out) {
    extern __shared__ float sm[];
    float* srcs = sm;                  // [pos][RPOS]
    float* wgt = sm + 144 * RPOS;      // [pixel 256][25]

    const int b = blockIdx.y;
    const int ti0 = (blockIdx.x >> 3) << 4;
    const int tj0 = (blockIdx.x & 7) << 4;
    const int tid = threadIdx.x;
    const int sy0 = (ti0 >> 1) - 2;
    const int sx0 = (tj0 >> 1) - 2;

    // stage x window into skewed subset layout
#pragma unroll 4
    for (int it = 0; it < 72; it++) {
        int idx = tid + it * 256;            // idx = c*144 + pos
        int c = idx / 144;
        int pos = idx - c * 144;
        int yy = pos / 12;
        int xx = pos - yy * 12;
        int gy = sy0 + yy, gx = sx0 + xx;
        float v = 0.f;
        if ((unsigned)gy < 64u && (unsigned)gx < 64u)
            v = x[((size_t)(b * CIN + c) << 12) + (gy << 6) + gx];
        int p = c >> 1;
        srcs[pos * RPOS + (p >> 4) * 36 + (p & 15) * 2 + (c & 1)] = v;
    }

    // softmax weights for this thread's pixel
    {
        int py = tid >> 4, px = tid & 15;
        int gi = ti0 + py, gj = tj0 + px;
        int y0 = gi >> 1, x0 = gj >> 1;
        int sub = ((gi & 1) << 1) | (gj & 1);
        float l[25];
        float mx = -1e30f;
#pragma unroll
        for (int k = 0; k < 25; k++) {
            int ch = (k << 2) + sub;
            float v = fmaf(g_t2[((size_t)(b * OC2 + ch) << 12) + (y0 << 6) + x0],
                           g_sc2[ch], g_sh2[ch]);
            l[k] = v;
            mx = fmaxf(mx, v);
        }
        float s = 0.f;
#pragma unroll
        for (int k = 0; k < 25; k++) { l[k] = expf(l[k] - mx); s += l[k]; }
        float inv = 1.f / s;
#pragma unroll
        for (int k = 0; k < 25; k++) wgt[tid * 25 + k] = l[k] * inv;
    }
    __syncthreads();

    const int s4 = tid & 3;           // channel subset
    const int quad = tid >> 2;        // 0..63
    const int qy = quad >> 3, qx = quad & 7;
    const int posb = qy * 12 + qx;
    const float* wp0 = &wgt[(2 * qy * 16 + 2 * qx) * 25];
    const int gi0 = ti0 + 2 * qy;
    const int gj = tj0 + 2 * qx;

#pragma unroll 1
    for (int g = 0; g < 2; g++) {
        u64 a[2][2][8];
#pragma unroll
        for (int di = 0; di < 2; di++)
#pragma unroll
            for (int dj = 0; dj < 2; dj++)
#pragma unroll
                for (int j = 0; j < 8; j++) a[di][dj][j] = 0ull;

#pragma unroll 1
        for (int dy = 0; dy < 5; dy++) {
#pragma unroll
            for (int dx = 0; dx < 5; dx++) {
                int k = dy * 5 + dx;
                float w00 = wp0[k], w01 = wp0[25 + k];
                float w10 = wp0[400 + k], w11 = wp0[425 + k];
                u64 W00 = pk(w00, w00), W01 = pk(w01, w01);
                u64 W10 = pk(w10, w10), W11 = pk(w11, w11);
                const ulonglong2* r = (const ulonglong2*)(
                    srcs + (posb + dy * 12 + dx) * RPOS + s4 * 36 + g * 16);
                ulonglong2 q0 = r[0], q1 = r[1], q2 = r[2], q3 = r[3];
                u64 sv[8] = {q0.x, q0.y, q1.x, q1.y, q2.x, q2.y, q3.x, q3.y};
#pragma unroll
                for (int j = 0; j < 8; j++) {
                    fma2(a[0][0][j], W00, sv[j]);
                    fma2(a[0][1][j], W01, sv[j]);
                    fma2(a[1][0][j], W10, sv[j]);
                    fma2(a[1][1][j], W11, sv[j]);
                }
            }
        }

#pragma unroll
        for (int j = 0; j < 8; j++) {
            int p = s4 * 16 + g * 8 + j;
            int c = 2 * p;
#pragma unroll
            for (int di = 0; di < 2; di++) {
                float e0, h0, e1, h1;
                unpk(a[di][0][j], e0, h0);
                unpk(a[di][1][j], e1, h1);
                size_t ob = (((size_t)(b * CIN + c) << 7) + gi0 + di) * 128 + gj;
                *(float2*)&out[ob] = make_float2(e0, e1);          // chan c
                *(float2*)&out[ob + 16384] = make_float2(h0, h1);  // chan c+1
            }
        }
    }
}

// ---------------------------------------------------------------------------
extern "C" void kernel_launch(void* const* d_in, const int* in_sizes, int n_in,
                              void* d_out, int out_size) {
    const float* x      = (const float*)d_in[0];
    const float* comp_w = (const float*)d_in[1];
    const float* comp_g = (const float*)d_in[2];
    const float* comp_b = (const float*)d_in[3];
    const float* enc_w  = (const float*)d_in[4];
    const float* enc_g  = (const float*)d_in[5];
    const float* enc_b  = (const float*)d_in[6];
    float* out = (float*)d_out;

    cudaFuncSetAttribute(k_conv3, cudaFuncAttributeMaxDynamicSharedMemorySize, CONV3_SMEM);
    cudaFuncSetAttribute(k_reasm, cudaFuncAttributeMaxDynamicSharedMemorySize, REASM_SMEM);

    k_prep<<<320, 256>>>(comp_w, enc_w);                 // 0
    k_conv1<<<dim3(16, B), 256>>>(x);                    // 1
    k_fin1<<<MID, 128>>>(comp_g, comp_b);                // 2
    k_conv3<<<dim3(32, B), 256, CONV3_SMEM>>>();         // 3  <- ncu slot
    k_fin2<<<OC2, 256>>>(enc_g, enc_b);                  // 4
    k_reasm<<<dim3(64, B), 256, REASM_SMEM>>>(x, out);   // 5
}